// round 2
// baseline (speedup 1.0000x reference)
#include <cuda_runtime.h>

// x: (16, 256, 128, 128) fp32, c = comp*64 + c4 (comp outer)
// out: (16, 256, 64, 64) fp32
// For each (b, c4, h2, w2): amp2[p] = sum_comp x[b, comp*64+c4, 2h2+kh, 2w2+kw]^2,
// p = kh*2+kw (kh,kw in 0..1); first argmax p; emit the 4 component values at p.

#define NB   16
#define NC4  64
#define HH   128
#define WW   128
#define H2   64
#define W2   64

__device__ __forceinline__ float pick2x2(const float4& t, const float4& bt, int idx, bool hi) {
    // hi=false: candidates t.x,t.y,bt.x,bt.y ; hi=true: t.z,t.w,bt.z,bt.w
    float c0 = hi ? t.z  : t.x;
    float c1 = hi ? t.w  : t.y;
    float c2 = hi ? bt.z : bt.x;
    float c3 = hi ? bt.w : bt.y;
    float v = c0;
    v = (idx == 1) ? c1 : v;
    v = (idx == 2) ? c2 : v;
    v = (idx == 3) ? c3 : v;
    return v;
}

__global__ __launch_bounds__(256)
void qmap_kernel(const float* __restrict__ x, float* __restrict__ out) {
    int tid = blockIdx.x * blockDim.x + threadIdx.x;
    // total threads = 16 * 64 * 32 * 32 = 1,048,576 ; each does 2 h2 rows' worth? No:
    // each thread handles h2 pair (h2a = 2*hh, h2b = 2*hh+1) and one w2-pair j.
    int j   = tid & 31;           // w2-pair: w2 = 2j, 2j+1; w base = 4j
    int hh  = (tid >> 5)  & 31;   // h2 pair: h2 = 2hh, 2hh+1
    int c4i = (tid >> 10) & 63;
    int b   = tid >> 16;

    const size_t plane       = (size_t)HH * WW;          // 16384
    const size_t comp_stride = (size_t)NC4 * plane;      // 64*16384

    size_t base = (size_t)(b * 4) * comp_stride
                + (size_t)c4i * plane
                + (size_t)(4 * hh) * WW                  // input row = 2*h2 = 4*hh
                + (size_t)(4 * j);

    // 16 independent 16B loads, front-batched for MLP
    float4 r0[4], r1[4], r2[4], r3[4];
#pragma unroll
    for (int cm = 0; cm < 4; cm++) {
        const float* p = x + base + (size_t)cm * comp_stride;
        r0[cm] = __ldcs(reinterpret_cast<const float4*>(p));
        r1[cm] = __ldcs(reinterpret_cast<const float4*>(p + WW));
        r2[cm] = __ldcs(reinterpret_cast<const float4*>(p + 2 * WW));
        r3[cm] = __ldcs(reinterpret_cast<const float4*>(p + 3 * WW));
    }

    // amp^2 per output pixel: 4 pixels (h2a/w2lo, h2a/w2hi, h2b/w2lo, h2b/w2hi)
    float aA[4] = {0.f, 0.f, 0.f, 0.f};   // h2a, pixel lo (cands r0.xy, r1.xy)
    float aB[4] = {0.f, 0.f, 0.f, 0.f};   // h2a, pixel hi (r0.zw, r1.zw)
    float aC[4] = {0.f, 0.f, 0.f, 0.f};   // h2b, pixel lo (r2.xy, r3.xy)
    float aD[4] = {0.f, 0.f, 0.f, 0.f};   // h2b, pixel hi (r2.zw, r3.zw)
#pragma unroll
    for (int cm = 0; cm < 4; cm++) {
        aA[0] = fmaf(r0[cm].x, r0[cm].x, aA[0]);
        aA[1] = fmaf(r0[cm].y, r0[cm].y, aA[1]);
        aA[2] = fmaf(r1[cm].x, r1[cm].x, aA[2]);
        aA[3] = fmaf(r1[cm].y, r1[cm].y, aA[3]);
        aB[0] = fmaf(r0[cm].z, r0[cm].z, aB[0]);
        aB[1] = fmaf(r0[cm].w, r0[cm].w, aB[1]);
        aB[2] = fmaf(r1[cm].z, r1[cm].z, aB[2]);
        aB[3] = fmaf(r1[cm].w, r1[cm].w, aB[3]);
        aC[0] = fmaf(r2[cm].x, r2[cm].x, aC[0]);
        aC[1] = fmaf(r2[cm].y, r2[cm].y, aC[1]);
        aC[2] = fmaf(r3[cm].x, r3[cm].x, aC[2]);
        aC[3] = fmaf(r3[cm].y, r3[cm].y, aC[3]);
        aD[0] = fmaf(r2[cm].z, r2[cm].z, aD[0]);
        aD[1] = fmaf(r2[cm].w, r2[cm].w, aD[1]);
        aD[2] = fmaf(r3[cm].z, r3[cm].z, aD[2]);
        aD[3] = fmaf(r3[cm].w, r3[cm].w, aD[3]);
    }

    // first-argmax (strict >)
    int iA = 0, iB = 0, iC = 0, iD = 0;
    {
        float m = aA[0];
        if (aA[1] > m) { m = aA[1]; iA = 1; }
        if (aA[2] > m) { m = aA[2]; iA = 2; }
        if (aA[3] > m) {            iA = 3; }
    }
    {
        float m = aB[0];
        if (aB[1] > m) { m = aB[1]; iB = 1; }
        if (aB[2] > m) { m = aB[2]; iB = 2; }
        if (aB[3] > m) {            iB = 3; }
    }
    {
        float m = aC[0];
        if (aC[1] > m) { m = aC[1]; iC = 1; }
        if (aC[2] > m) { m = aC[2]; iC = 2; }
        if (aC[3] > m) {            iC = 3; }
    }
    {
        float m = aD[0];
        if (aD[1] > m) { m = aD[1]; iD = 1; }
        if (aD[2] > m) { m = aD[2]; iD = 2; }
        if (aD[3] > m) {            iD = 3; }
    }

    const size_t oplane       = (size_t)H2 * W2;         // 4096
    const size_t ocomp_stride = (size_t)NC4 * oplane;    // 64*4096
    size_t obase = (size_t)(b * 4) * ocomp_stride
                 + (size_t)c4i * oplane
                 + (size_t)(2 * hh) * W2                 // h2a row
                 + (size_t)(2 * j);

#pragma unroll
    for (int cm = 0; cm < 4; cm++) {
        float vA = pick2x2(r0[cm], r1[cm], iA, false);
        float vB = pick2x2(r0[cm], r1[cm], iB, true);
        float vC = pick2x2(r2[cm], r3[cm], iC, false);
        float vD = pick2x2(r2[cm], r3[cm], iD, true);
        float* po = out + obase + (size_t)cm * ocomp_stride;
        __stcs(reinterpret_cast<float2*>(po),       make_float2(vA, vB));
        __stcs(reinterpret_cast<float2*>(po + W2),  make_float2(vC, vD));
    }
}

extern "C" void kernel_launch(void* const* d_in, const int* in_sizes, int n_in,
                              void* d_out, int out_size) {
    const float* x = (const float*)d_in[0];
    float* out = (float*)d_out;
    const int total = NB * NC4 * (H2 / 2) * (W2 / 2);   // 1,048,576 threads
    const int block = 256;
    const int grid  = total / block;                    // 4096
    qmap_kernel<<<grid, block>>>(x, out);
}

// round 3
// speedup vs baseline: 1.0125x; 1.0125x over previous
#include <cuda_runtime.h>

// x: (16, 256, 128, 128) fp32, c = comp*64 + c4 (comp outer)
// out: (16, 256, 64, 64) fp32
// For each (b, c4, h2, w2): amp2[p] = sum_comp x[b, comp*64+c4, 2h2+kh, 2w2+kw]^2,
// p = kh*2+kw; first argmax p (strict >); emit the 4 component values at p.

#define NB   16
#define NC4  64
#define HH   128
#define WW   128
#define H2   64
#define W2   64

__device__ __forceinline__ float pick2x2(const float4& t, const float4& bt, int idx, bool hi) {
    float c0 = hi ? t.z  : t.x;
    float c1 = hi ? t.w  : t.y;
    float c2 = hi ? bt.z : bt.x;
    float c3 = hi ? bt.w : bt.y;
    float v = c0;
    v = (idx == 1) ? c1 : v;
    v = (idx == 2) ? c2 : v;
    v = (idx == 3) ? c3 : v;
    return v;
}

__global__ __launch_bounds__(256)
void qmap_kernel(const float* __restrict__ x, float* __restrict__ out) {
    int tid = blockIdx.x * blockDim.x + threadIdx.x;
    // total threads = 16 * 64 * 64 * 32 = 2,097,152
    int j   = tid & 31;           // w2-pair: w2 = 2j, 2j+1; input w base = 4j
    int h2  = (tid >> 5)  & 63;
    int c4i = (tid >> 11) & 63;
    int b   = tid >> 17;

    const size_t plane       = (size_t)HH * WW;          // 16384
    const size_t comp_stride = (size_t)NC4 * plane;      // 64*16384

    size_t base = (size_t)(b * 4) * comp_stride
                + (size_t)c4i * plane
                + (size_t)(2 * h2) * WW
                + (size_t)(4 * j);

    // 8 independent 16B loads, front-batched (default cache policy: L2 can
    // merge/absorb the streaming reads; .cs measured slightly worse).
    float4 r0[4], r1[4];
#pragma unroll
    for (int cm = 0; cm < 4; cm++) {
        const float* p = x + base + (size_t)cm * comp_stride;
        r0[cm] = *reinterpret_cast<const float4*>(p);
        r1[cm] = *reinterpret_cast<const float4*>(p + WW);
    }

    // amp^2 for pixel lo (r0.xy, r1.xy) and pixel hi (r0.zw, r1.zw)
    float aA[4] = {0.f, 0.f, 0.f, 0.f};
    float aB[4] = {0.f, 0.f, 0.f, 0.f};
#pragma unroll
    for (int cm = 0; cm < 4; cm++) {
        aA[0] = fmaf(r0[cm].x, r0[cm].x, aA[0]);
        aA[1] = fmaf(r0[cm].y, r0[cm].y, aA[1]);
        aA[2] = fmaf(r1[cm].x, r1[cm].x, aA[2]);
        aA[3] = fmaf(r1[cm].y, r1[cm].y, aA[3]);
        aB[0] = fmaf(r0[cm].z, r0[cm].z, aB[0]);
        aB[1] = fmaf(r0[cm].w, r0[cm].w, aB[1]);
        aB[2] = fmaf(r1[cm].z, r1[cm].z, aB[2]);
        aB[3] = fmaf(r1[cm].w, r1[cm].w, aB[3]);
    }

    int iA = 0, iB = 0;
    {
        float m = aA[0];
        if (aA[1] > m) { m = aA[1]; iA = 1; }
        if (aA[2] > m) { m = aA[2]; iA = 2; }
        if (aA[3] > m) {            iA = 3; }
    }
    {
        float m = aB[0];
        if (aB[1] > m) { m = aB[1]; iB = 1; }
        if (aB[2] > m) { m = aB[2]; iB = 2; }
        if (aB[3] > m) {            iB = 3; }
    }

    const size_t oplane       = (size_t)H2 * W2;         // 4096
    const size_t ocomp_stride = (size_t)NC4 * oplane;    // 64*4096
    size_t obase = (size_t)(b * 4) * ocomp_stride
                 + (size_t)c4i * oplane
                 + (size_t)h2 * W2
                 + (size_t)(2 * j);

#pragma unroll
    for (int cm = 0; cm < 4; cm++) {
        float vA = pick2x2(r0[cm], r1[cm], iA, false);
        float vB = pick2x2(r0[cm], r1[cm], iB, true);
        // streaming store: evict-first, keep L2 for the read stream
        __stcs(reinterpret_cast<float2*>(out + obase + (size_t)cm * ocomp_stride),
               make_float2(vA, vB));
    }
}

extern "C" void kernel_launch(void* const* d_in, const int* in_sizes, int n_in,
                              void* d_out, int out_size) {
    const float* x = (const float*)d_in[0];
    float* out = (float*)d_out;
    const int total = NB * NC4 * H2 * (W2 / 2);   // 2,097,152 threads
    const int block = 256;
    const int grid  = total / block;              // 8192
    qmap_kernel<<<grid, block>>>(x, out);
}